// round 1
// baseline (speedup 1.0000x reference)
#include <cuda_runtime.h>
#include <math.h>

#define BB 8
#define SS 4096
#define EE 2048
#define DD 128
#define MM (BB*SS)   // 32768

// Scratch for projected q, k, v (allocation-free: __device__ globals)
__device__ float g_q[MM*DD];
__device__ float g_k[MM*DD];
__device__ float g_v[MM*DD];

typedef unsigned long long u64;

// ---- packed f32x2 helpers (sm_103a FFMA2 path, PTX-only) ----
__device__ __forceinline__ u64 ffma2(u64 a, u64 b, u64 c) {
    u64 d;
    asm("fma.rn.f32x2 %0, %1, %2, %3;" : "=l"(d) : "l"(a), "l"(b), "l"(c));
    return d;
}
__device__ __forceinline__ u64 fmul2(u64 a, u64 b) {
    u64 d;
    asm("mul.rn.f32x2 %0, %1, %2;" : "=l"(d) : "l"(a), "l"(b));
    return d;
}
__device__ __forceinline__ u64 pack2(float x, float y) {
    u64 d; asm("mov.b64 %0, {%1, %2};" : "=l"(d) : "f"(x), "f"(y)); return d;
}
__device__ __forceinline__ float2 unpack2(u64 v) {
    float2 r; asm("mov.b64 {%0, %1}, %2;" : "=f"(r.x), "=f"(r.y) : "l"(v)); return r;
}

// ============================================================================
// Kernel 1: QKV projection. out[m][n] = sum_k x[m][k]*W[k][n] + b[n]
// Block tile 128(M) x 128(N=D), K-step 8, 256 threads, micro 8x8 per thread.
// grid.y in {0,1,2} selects (Wq,bq,g_q) / (Wk,bk,g_k) / (Wv,bv,g_v).
// ============================================================================
__global__ __launch_bounds__(256) void qkv_gemm(
    const float* __restrict__ x,
    const float* __restrict__ Wq, const float* __restrict__ bq,
    const float* __restrict__ Wk, const float* __restrict__ bk,
    const float* __restrict__ Wv, const float* __restrict__ bv)
{
    const float* W; const float* bias; float* out;
    if (blockIdx.y == 0)      { W = Wq; bias = bq; out = g_q; }
    else if (blockIdx.y == 1) { W = Wk; bias = bk; out = g_k; }
    else                      { W = Wv; bias = bv; out = g_v; }

    __shared__ float xs[2][8][128];   // [buf][k][m]
    __shared__ float ws[2][8][128];   // [buf][k][n]

    const int tid = threadIdx.x;
    const int ty = tid >> 4;          // 0..15 (m groups of 8)
    const int tx = tid & 15;          // 0..15 (n groups: cols tx*4 and 64+tx*4)
    const int m0 = blockIdx.x * 128;

    // loader indices
    const int lxr = tid >> 1;             // 0..127 : x tile row
    const int lxc = (tid & 1) * 4;        // 0 or 4 : k sub-chunk
    const int lwr = tid >> 5;             // 0..7   : w tile k-row
    const int lwc = (tid & 31) * 4;       // 0..124 : w col

    const float* xg = x + (long long)(m0 + lxr) * EE + lxc;
    const float* wg = W + (long long)lwr * DD + lwc;

    u64 acc[8][4];
    #pragma unroll
    for (int i = 0; i < 8; i++)
        #pragma unroll
        for (int j = 0; j < 4; j++) acc[i][j] = 0ull;

    // prologue: tile 0
    float4 xr = *(const float4*)xg;
    float4 wr = *(const float4*)wg;
    xs[0][lxc+0][lxr] = xr.x; xs[0][lxc+1][lxr] = xr.y;
    xs[0][lxc+2][lxr] = xr.z; xs[0][lxc+3][lxr] = xr.w;
    *(float4*)&ws[0][lwr][lwc] = wr;
    __syncthreads();

    int buf = 0;
    const int NT = EE / 8;   // 256
    for (int kt = 0; kt < NT; kt++) {
        if (kt + 1 < NT) {
            xr = *(const float4*)(xg + (kt + 1) * 8);
            wr = *(const float4*)(wg + (long long)(kt + 1) * 8 * DD);
        }
        #pragma unroll
        for (int k = 0; k < 8; k++) {
            float4 a0 = *(float4*)&xs[buf][k][ty*8];
            float4 a1 = *(float4*)&xs[buf][k][ty*8+4];
            float4 b0 = *(float4*)&ws[buf][k][tx*4];
            float4 b1 = *(float4*)&ws[buf][k][64 + tx*4];
            u64 bb0 = pack2(b0.x, b0.y), bb1 = pack2(b0.z, b0.w);
            u64 bb2 = pack2(b1.x, b1.y), bb3 = pack2(b1.z, b1.w);
            float av[8] = {a0.x,a0.y,a0.z,a0.w,a1.x,a1.y,a1.z,a1.w};
            #pragma unroll
            for (int i = 0; i < 8; i++) {
                u64 a2 = pack2(av[i], av[i]);
                acc[i][0] = ffma2(a2, bb0, acc[i][0]);
                acc[i][1] = ffma2(a2, bb1, acc[i][1]);
                acc[i][2] = ffma2(a2, bb2, acc[i][2]);
                acc[i][3] = ffma2(a2, bb3, acc[i][3]);
            }
        }
        if (kt + 1 < NT) {
            int nb = buf ^ 1;
            xs[nb][lxc+0][lxr] = xr.x; xs[nb][lxc+1][lxr] = xr.y;
            xs[nb][lxc+2][lxr] = xr.z; xs[nb][lxc+3][lxr] = xr.w;
            *(float4*)&ws[nb][lwr][lwc] = wr;
        }
        __syncthreads();
        buf ^= 1;
    }

    // epilogue: +bias, store
    float4 bl = *(const float4*)&bias[tx*4];
    float4 bh = *(const float4*)&bias[64 + tx*4];
    #pragma unroll
    for (int i = 0; i < 8; i++) {
        float2 p0 = unpack2(acc[i][0]), p1 = unpack2(acc[i][1]);
        float2 p2 = unpack2(acc[i][2]), p3 = unpack2(acc[i][3]);
        float4 o0 = make_float4(p0.x + bl.x, p0.y + bl.y, p1.x + bl.z, p1.y + bl.w);
        float4 o1 = make_float4(p2.x + bh.x, p2.y + bh.y, p3.x + bh.z, p3.y + bh.w);
        long long row = m0 + ty*8 + i;
        *(float4*)(out + row * DD + tx*4)      = o0;
        *(float4*)(out + row * DD + 64 + tx*4) = o1;
    }
}

// ============================================================================
// Kernel 2: flash attention, Br=Bc=64, D=128, fp32, online softmax.
// 256 threads = 16x16 grid. Score micro 4(i) x 4(j); O micro 4(i) x 8(d).
// ============================================================================
#define BR 64
#define BC 64
#define PSTR 68   // P smem row stride (float4-aligned, conflict-light)

__global__ __launch_bounds__(256) void flash_attn(float* __restrict__ out)
{
    extern __shared__ float sm[];
    float* Qs = sm;                 // [64][128]
    float* Kt = Qs + BR * DD;       // [128][64]  (transposed K tile)
    float* Vs = Kt + DD * BC;       // [64][128]
    float* Ps = Vs + BC * DD;       // [64][PSTR]

    const int tid = threadIdx.x;
    const int ty = tid >> 4;        // 0..15 -> rows ty*4..+3
    const int tx = tid & 15;        // 0..15 -> score cols tx*4..+3 ; O cols tx*4 & 64+tx*4
    const int b = blockIdx.y;
    const int qi0 = blockIdx.x * BR;

    const float* qg  = g_q + ((long long)b * SS + qi0) * DD;
    const float* kgb = g_k + (long long)b * SS * DD;
    const float* vgb = g_v + (long long)b * SS * DD;

    // load Q tile
    for (int idx = tid; idx < BR * DD / 4; idx += 256) {
        int r = idx >> 5, c4 = (idx & 31) << 2;
        *(float4*)&Qs[r * DD + c4] = *(const float4*)(qg + (long long)r * DD + c4);
    }

    u64 o2[4][4];
    #pragma unroll
    for (int r = 0; r < 4; r++)
        #pragma unroll
        for (int j = 0; j < 4; j++) o2[r][j] = 0ull;
    float m_i[4] = {-INFINITY, -INFINITY, -INFINITY, -INFINITY};
    float l_i[4] = {0.f, 0.f, 0.f, 0.f};

    __syncthreads();

    for (int kt = 0; kt < SS / BC; kt++) {
        // ---- load K (transposed) and V tiles ----
        const float* kg = kgb + (long long)kt * BC * DD;
        const float* vg = vgb + (long long)kt * BC * DD;
        for (int idx = tid; idx < BC * DD / 4; idx += 256) {
            int j = idx >> 5, c4 = (idx & 31) << 2;
            float4 kv = *(const float4*)(kg + (long long)j * DD + c4);
            Kt[(c4+0) * BC + j] = kv.x;
            Kt[(c4+1) * BC + j] = kv.y;
            Kt[(c4+2) * BC + j] = kv.z;
            Kt[(c4+3) * BC + j] = kv.w;
            *(float4*)&Vs[j * DD + c4] = *(const float4*)(vg + (long long)j * DD + c4);
        }
        __syncthreads();

        // ---- S = Q K^T  (4x4 per thread, packed along j) ----
        u64 s2[4][2];
        #pragma unroll
        for (int r = 0; r < 4; r++) { s2[r][0] = 0ull; s2[r][1] = 0ull; }

        for (int d = 0; d < DD; d += 4) {
            float4 kk0 = *(float4*)&Kt[(d+0) * BC + tx*4];
            float4 kk1 = *(float4*)&Kt[(d+1) * BC + tx*4];
            float4 kk2 = *(float4*)&Kt[(d+2) * BC + tx*4];
            float4 kk3 = *(float4*)&Kt[(d+3) * BC + tx*4];
            u64 kp[4][2] = {
                { pack2(kk0.x,kk0.y), pack2(kk0.z,kk0.w) },
                { pack2(kk1.x,kk1.y), pack2(kk1.z,kk1.w) },
                { pack2(kk2.x,kk2.y), pack2(kk2.z,kk2.w) },
                { pack2(kk3.x,kk3.y), pack2(kk3.z,kk3.w) },
            };
            #pragma unroll
            for (int r = 0; r < 4; r++) {
                float4 qq = *(float4*)&Qs[(ty*4 + r) * DD + d];
                float qv[4] = {qq.x, qq.y, qq.z, qq.w};
                #pragma unroll
                for (int dd = 0; dd < 4; dd++) {
                    u64 q2 = pack2(qv[dd], qv[dd]);
                    s2[r][0] = ffma2(q2, kp[dd][0], s2[r][0]);
                    s2[r][1] = ffma2(q2, kp[dd][1], s2[r][1]);
                }
            }
        }

        // ---- online softmax update ----
        float p[4][4];
        #pragma unroll
        for (int r = 0; r < 4; r++) {
            float2 a = unpack2(s2[r][0]), c = unpack2(s2[r][1]);
            p[r][0] = a.x; p[r][1] = a.y; p[r][2] = c.x; p[r][3] = c.y;
        }
        #pragma unroll
        for (int r = 0; r < 4; r++) {
            float mx = fmaxf(fmaxf(p[r][0], p[r][1]), fmaxf(p[r][2], p[r][3]));
            #pragma unroll
            for (int w = 1; w < 16; w <<= 1)
                mx = fmaxf(mx, __shfl_xor_sync(0xffffffffu, mx, w));
            float mnew = fmaxf(m_i[r], mx);
            float scale = __expf(m_i[r] - mnew);
            m_i[r] = mnew;
            float rs = 0.f;
            #pragma unroll
            for (int c = 0; c < 4; c++) { p[r][c] = __expf(p[r][c] - mnew); rs += p[r][c]; }
            #pragma unroll
            for (int w = 1; w < 16; w <<= 1)
                rs += __shfl_xor_sync(0xffffffffu, rs, w);
            l_i[r] = l_i[r] * scale + rs;
            u64 sc2 = pack2(scale, scale);
            #pragma unroll
            for (int j = 0; j < 4; j++) o2[r][j] = fmul2(o2[r][j], sc2);
        }

        // ---- stage P ----
        #pragma unroll
        for (int r = 0; r < 4; r++)
            *(float4*)&Ps[(ty*4 + r) * PSTR + tx*4] =
                make_float4(p[r][0], p[r][1], p[r][2], p[r][3]);
        __syncthreads();

        // ---- O += P @ V  (cols tx*4 and 64+tx*4, packed along d) ----
        for (int j = 0; j < BC; j += 4) {
            float4 pr[4];
            #pragma unroll
            for (int r = 0; r < 4; r++)
                pr[r] = *(float4*)&Ps[(ty*4 + r) * PSTR + j];
            #pragma unroll
            for (int jj = 0; jj < 4; jj++) {
                float4 va = *(float4*)&Vs[(j+jj) * DD + tx*4];
                float4 vb = *(float4*)&Vs[(j+jj) * DD + 64 + tx*4];
                u64 v0 = pack2(va.x, va.y), v1 = pack2(va.z, va.w);
                u64 v2 = pack2(vb.x, vb.y), v3 = pack2(vb.z, vb.w);
                #pragma unroll
                for (int r = 0; r < 4; r++) {
                    float pv = (jj == 0) ? pr[r].x : (jj == 1) ? pr[r].y
                             : (jj == 2) ? pr[r].z : pr[r].w;
                    u64 p2v = pack2(pv, pv);
                    o2[r][0] = ffma2(p2v, v0, o2[r][0]);
                    o2[r][1] = ffma2(p2v, v1, o2[r][1]);
                    o2[r][2] = ffma2(p2v, v2, o2[r][2]);
                    o2[r][3] = ffma2(p2v, v3, o2[r][3]);
                }
            }
        }
        __syncthreads();   // protect Kt/Vs/Ps before next tile
    }

    // ---- epilogue: normalize + store ----
    #pragma unroll
    for (int r = 0; r < 4; r++) {
        float inv = 1.0f / l_i[r];
        u64 inv2 = pack2(inv, inv);
        float2 a0 = unpack2(fmul2(o2[r][0], inv2));
        float2 a1 = unpack2(fmul2(o2[r][1], inv2));
        float2 a2 = unpack2(fmul2(o2[r][2], inv2));
        float2 a3 = unpack2(fmul2(o2[r][3], inv2));
        long long row = (long long)b * SS + qi0 + ty*4 + r;
        *(float4*)(out + row * DD + tx*4)      = make_float4(a0.x, a0.y, a1.x, a1.y);
        *(float4*)(out + row * DD + 64 + tx*4) = make_float4(a2.x, a2.y, a3.x, a3.y);
    }
}

// ============================================================================
// launch
// ============================================================================
extern "C" void kernel_launch(void* const* d_in, const int* in_sizes, int n_in,
                              void* d_out, int out_size)
{
    const float* x  = (const float*)d_in[0];
    const float* Wq = (const float*)d_in[1];
    const float* bq = (const float*)d_in[2];
    const float* Wk = (const float*)d_in[3];
    const float* bk = (const float*)d_in[4];
    const float* Wv = (const float*)d_in[5];
    const float* bv = (const float*)d_in[6];
    float* out = (float*)d_out;

    qkv_gemm<<<dim3(MM / 128, 3), 256>>>(x, Wq, bq, Wk, bk, Wv, bv);

    const int smem_bytes = (BR*DD + DD*BC + BC*DD + BR*PSTR) * (int)sizeof(float);
    cudaFuncSetAttribute(flash_attn, cudaFuncAttributeMaxDynamicSharedMemorySize,
                         smem_bytes);
    flash_attn<<<dim3(SS / BR, BB), 256, smem_bytes>>>(out);
}

// round 3
// speedup vs baseline: 2.4316x; 2.4316x over previous
#include <cuda_runtime.h>
#include <cuda_fp16.h>
#include <math.h>
#include <stdint.h>

#define BB 8
#define SS 4096
#define EE 2048
#define DD 128
#define MM (BB*SS)   // 32768

// fp16 hi/lo scratch (allocation-free __device__ globals)
__device__ __half g_qh[MM*DD];
__device__ __half g_ql[MM*DD];
__device__ __half g_kh[MM*DD];
__device__ __half g_kl[MM*DD];
__device__ __half g_vth[MM*DD];   // transposed: [b][d][s]
__device__ __half g_vtl[MM*DD];

typedef unsigned long long u64;

// ---- packed f32x2 helpers (FFMA2 path for the QKV GEMM) ----
__device__ __forceinline__ u64 ffma2(u64 a, u64 b, u64 c) {
    u64 d; asm("fma.rn.f32x2 %0, %1, %2, %3;" : "=l"(d) : "l"(a), "l"(b), "l"(c)); return d;
}
__device__ __forceinline__ u64 pack2(float x, float y) {
    u64 d; asm("mov.b64 %0, {%1, %2};" : "=l"(d) : "f"(x), "f"(y)); return d;
}
__device__ __forceinline__ float2 unpack2(u64 v) {
    float2 r; asm("mov.b64 {%0, %1}, %2;" : "=f"(r.x), "=f"(r.y) : "l"(v)); return r;
}
__device__ __forceinline__ uint32_t pack_h2(float a, float b) {
    __half ha = __float2half_rn(a), hb = __float2half_rn(b);
    return ((uint32_t)__half_as_ushort(hb) << 16) | (uint32_t)__half_as_ushort(ha);
}

__device__ __forceinline__ uint32_t smem_u32(const void* p) {
    uint32_t a;
    asm("{ .reg .u64 t; cvta.to.shared.u64 t, %1; cvt.u32.u64 %0, t; }" : "=r"(a) : "l"(p));
    return a;
}

// ---- sm_80-era primitives (valid on base compute_103) ----
__device__ __forceinline__ void cp16(uint32_t dst, const void* src) {
    asm volatile("cp.async.cg.shared.global [%0], [%1], 16;" :: "r"(dst), "l"(src));
}
#define CP_COMMIT() asm volatile("cp.async.commit_group;" ::: "memory")
#define CP_WAIT0()  asm volatile("cp.async.wait_group 0;" ::: "memory")

__device__ __forceinline__ void ldsm4(uint32_t r[4], uint32_t addr) {
    asm volatile("ldmatrix.sync.aligned.m8n8.x4.shared.b16 {%0,%1,%2,%3}, [%4];"
        : "=r"(r[0]), "=r"(r[1]), "=r"(r[2]), "=r"(r[3]) : "r"(addr));
}
__device__ __forceinline__ void mma16816(float c[4], const uint32_t a[4],
                                          uint32_t b0, uint32_t b1) {
    asm volatile("mma.sync.aligned.m16n8k16.row.col.f32.f16.f16.f32 "
        "{%0,%1,%2,%3}, {%4,%5,%6,%7}, {%8,%9}, {%0,%1,%2,%3};"
        : "+f"(c[0]), "+f"(c[1]), "+f"(c[2]), "+f"(c[3])
        : "r"(a[0]), "r"(a[1]), "r"(a[2]), "r"(a[3]), "r"(b0), "r"(b1));
}

// ============================================================================
// Kernel 1: QKV projection (FFMA2 fp32). Epilogue: fp16 hi/lo split.
// V stored TRANSPOSED [b][d][s] so PV's B operand loads as [n=d][k=key].
// ============================================================================
__global__ __launch_bounds__(256) void qkv_gemm(
    const float* __restrict__ x,
    const float* __restrict__ Wq, const float* __restrict__ bq,
    const float* __restrict__ Wk, const float* __restrict__ bk,
    const float* __restrict__ Wv, const float* __restrict__ bv)
{
    const float* W; const float* bias;
    if (blockIdx.y == 0)      { W = Wq; bias = bq; }
    else if (blockIdx.y == 1) { W = Wk; bias = bk; }
    else                      { W = Wv; bias = bv; }

    __shared__ float xs[2][8][128];
    __shared__ float ws[2][8][128];

    const int tid = threadIdx.x;
    const int ty = tid >> 4;
    const int tx = tid & 15;
    const int m0 = blockIdx.x * 128;

    const int lxr = tid >> 1;
    const int lxc = (tid & 1) * 4;
    const int lwr = tid >> 5;
    const int lwc = (tid & 31) * 4;

    const float* xg = x + (long long)(m0 + lxr) * EE + lxc;
    const float* wg = W + (long long)lwr * DD + lwc;

    u64 acc[8][4];
    #pragma unroll
    for (int i = 0; i < 8; i++)
        #pragma unroll
        for (int j = 0; j < 4; j++) acc[i][j] = 0ull;

    float4 xr = *(const float4*)xg;
    float4 wr = *(const float4*)wg;
    xs[0][lxc+0][lxr] = xr.x; xs[0][lxc+1][lxr] = xr.y;
    xs[0][lxc+2][lxr] = xr.z; xs[0][lxc+3][lxr] = xr.w;
    *(float4*)&ws[0][lwr][lwc] = wr;
    __syncthreads();

    int buf = 0;
    const int NTk = EE / 8;
    for (int kt = 0; kt < NTk; kt++) {
        if (kt + 1 < NTk) {
            xr = *(const float4*)(xg + (kt + 1) * 8);
            wr = *(const float4*)(wg + (long long)(kt + 1) * 8 * DD);
        }
        #pragma unroll
        for (int k = 0; k < 8; k++) {
            float4 a0 = *(float4*)&xs[buf][k][ty*8];
            float4 a1 = *(float4*)&xs[buf][k][ty*8+4];
            float4 b0 = *(float4*)&ws[buf][k][tx*4];
            float4 b1 = *(float4*)&ws[buf][k][64 + tx*4];
            u64 bb0 = pack2(b0.x, b0.y), bb1 = pack2(b0.z, b0.w);
            u64 bb2 = pack2(b1.x, b1.y), bb3 = pack2(b1.z, b1.w);
            float av[8] = {a0.x,a0.y,a0.z,a0.w,a1.x,a1.y,a1.z,a1.w};
            #pragma unroll
            for (int i = 0; i < 8; i++) {
                u64 a2 = pack2(av[i], av[i]);
                acc[i][0] = ffma2(a2, bb0, acc[i][0]);
                acc[i][1] = ffma2(a2, bb1, acc[i][1]);
                acc[i][2] = ffma2(a2, bb2, acc[i][2]);
                acc[i][3] = ffma2(a2, bb3, acc[i][3]);
            }
        }
        if (kt + 1 < NTk) {
            int nb = buf ^ 1;
            xs[nb][lxc+0][lxr] = xr.x; xs[nb][lxc+1][lxr] = xr.y;
            xs[nb][lxc+2][lxr] = xr.z; xs[nb][lxc+3][lxr] = xr.w;
            *(float4*)&ws[nb][lwr][lwc] = wr;
        }
        __syncthreads();
        buf ^= 1;
    }

    float4 bl = *(const float4*)&bias[tx*4];
    float4 bh = *(const float4*)&bias[64 + tx*4];

    #pragma unroll
    for (int i = 0; i < 8; i++) {
        float2 p0 = unpack2(acc[i][0]), p1 = unpack2(acc[i][1]);
        float2 p2 = unpack2(acc[i][2]), p3 = unpack2(acc[i][3]);
        float v[8];
        v[0] = p0.x + bl.x; v[1] = p0.y + bl.y; v[2] = p1.x + bl.z; v[3] = p1.y + bl.w;
        v[4] = p2.x + bh.x; v[5] = p2.y + bh.y; v[6] = p3.x + bh.z; v[7] = p3.y + bh.w;
        const int tok = m0 + ty*8 + i;

        float hi[8], lo[8];
        #pragma unroll
        for (int c = 0; c < 8; c++) {
            __half h = __float2half_rn(v[c]);
            hi[c] = __half2float(h);
            lo[c] = v[c] - hi[c];
        }

        if (blockIdx.y < 2) {
            __half* ph = (blockIdx.y == 0) ? g_qh : g_kh;
            __half* pl = (blockIdx.y == 0) ? g_ql : g_kl;
            uint2 uh0 = make_uint2(pack_h2(hi[0], hi[1]), pack_h2(hi[2], hi[3]));
            uint2 uh1 = make_uint2(pack_h2(hi[4], hi[5]), pack_h2(hi[6], hi[7]));
            uint2 ul0 = make_uint2(pack_h2(lo[0], lo[1]), pack_h2(lo[2], lo[3]));
            uint2 ul1 = make_uint2(pack_h2(lo[4], lo[5]), pack_h2(lo[6], lo[7]));
            long long base = (long long)tok * DD;
            *(uint2*)&ph[base + tx*4]      = uh0;
            *(uint2*)&ph[base + 64 + tx*4] = uh1;
            *(uint2*)&pl[base + tx*4]      = ul0;
            *(uint2*)&pl[base + 64 + tx*4] = ul1;
        } else {
            const int bbx = tok >> 12;
            const int spos = tok & 4095;
            #pragma unroll
            for (int c = 0; c < 8; c++) {
                int col = (c < 4) ? (tx*4 + c) : (64 + tx*4 + (c - 4));
                long long idx = ((long long)bbx * DD + col) * SS + spos;
                g_vth[idx] = __float2half_rn(hi[c]);
                g_vtl[idx] = __float2half_rn(lo[c]);
            }
        }
    }
}

// ============================================================================
// Kernel 2: mma.sync flash attention.
// 128 q-rows/CTA (8 warps x 16 rows), 64 keys/tile, D=128.
//   S  = Qh*Kh + Ql*Kh + Qh*Kl     (fp32 mma accum)
//   PV = Ph*Vh + Pl*Vh + Ph*Vl     (fp32 mma accum, P frags reused from C layout)
// K/V double-buffered via cp.async.
// ============================================================================
#define QT 128
#define KT 64
#define NTILE (SS/KT)   // 64
#define QSTR 136        // halfs per row (+8 pad -> conflict-free LDSM)
#define KSTR 136
#define VSTR 72

#define OFF_QH 0
#define OFF_QL (128*QSTR*2)             // 34816
#define OFF_K  (OFF_QL + 128*QSTR*2)    // 69632
#define KBUF   (64*KSTR*2*2)            // 34816 (Kh+Kl per buffer)
#define KLOFF  (64*KSTR*2)              // 17408
#define OFF_V  (OFF_K + 2*KBUF)         // 139264
#define VBUF   (128*VSTR*2*2)           // 36864 (Vh+Vl per buffer)
#define VLOFF  (128*VSTR*2)             // 18432
#define FLASH_SMEM (OFF_V + 2*VBUF)     // 212992

__device__ __forceinline__ void load_kv(uint32_t smem, int b, int kt, int buf, int tid) {
    long long tok0 = (long long)b * SS + (long long)kt * KT;
    #pragma unroll
    for (int it = 0; it < 8; it++) {
        int ci = tid + it * 256;           // 0..2047
        int c = ci & 15;
        int row = (ci >> 4) & 63;
        const __half* src = ((ci < 1024) ? g_kh : g_kl) + (tok0 + row) * DD + c * 8;
        uint32_t dst = smem + OFF_K + buf * KBUF + ((ci < 1024) ? 0 : KLOFF)
                       + row * (KSTR*2) + c * 16;
        cp16(dst, src);
    }
    long long vbase = (long long)b * DD * SS + (long long)kt * KT;
    #pragma unroll
    for (int it = 0; it < 8; it++) {
        int ci = tid + it * 256;           // 0..2047
        int c = ci & 7;
        int d = (ci >> 3) & 127;
        const __half* src = ((ci < 1024) ? g_vth : g_vtl) + vbase + (long long)d * SS + c * 8;
        uint32_t dst = smem + OFF_V + buf * VBUF + ((ci < 1024) ? 0 : VLOFF)
                       + d * (VSTR*2) + c * 16;
        cp16(dst, src);
    }
}

__global__ __launch_bounds__(256, 1) void flash_attn(float* __restrict__ out)
{
    extern __shared__ char sm[];
    const uint32_t smem = smem_u32(sm);
    const int tid = threadIdx.x;
    const int w = tid >> 5;
    const int l = tid & 31;
    const int b = blockIdx.y;
    const int qi0 = blockIdx.x * QT;

    // ---- prologue: Q (once) + K/V tile 0 via cp.async ----
    {
        long long tok0 = (long long)b * SS + qi0;
        #pragma unroll
        for (int it = 0; it < 16; it++) {
            int ci = tid + it * 256;       // 0..4095
            int c = ci & 15;
            int row = (ci >> 4) & 127;
            const __half* src = ((ci < 2048) ? g_qh : g_ql) + (tok0 + row) * DD + c * 8;
            uint32_t dst = smem + ((ci < 2048) ? OFF_QH : OFF_QL) + row * (QSTR*2) + c * 16;
            cp16(dst, src);
        }
    }
    load_kv(smem, b, 0, 0, tid);
    CP_COMMIT();
    CP_WAIT0();
    __syncthreads();

    float of[16][4];
    #pragma unroll
    for (int n = 0; n < 16; n++)
        #pragma unroll
        for (int c = 0; c < 4; c++) of[n][c] = 0.f;
    float m0 = -INFINITY, m1 = -INFINITY, l0 = 0.f, l1 = 0.f;

    // per-lane fragment address pieces
    const uint32_t qoff  = smem + (w*16 + (l & 15)) * (QSTR*2) + ((l >> 4) * 16);
    const uint32_t brow  = (l & 7) + ((l >> 4) & 1) * 8;          // B-frag row-in-block
    const uint32_t bcsel = ((l >> 3) & 1) * 16;                   // B-frag k byte offset

    for (int t = 0; t < NTILE; t++) {
        if (t + 1 < NTILE) load_kv(smem, b, t + 1, (t + 1) & 1, tid);
        CP_COMMIT();

        const uint32_t kb = smem + OFF_K + (t & 1) * KBUF;
        const uint32_t vb = smem + OFF_V + (t & 1) * VBUF;

        // ---- S = Q K^T ----
        float sf[8][4];
        #pragma unroll
        for (int j = 0; j < 8; j++)
            #pragma unroll
            for (int c = 0; c < 4; c++) sf[j][c] = 0.f;

        #pragma unroll
        for (int kc = 0; kc < 8; kc++) {
            uint32_t ah[4], al[4];
            ldsm4(ah, qoff + OFF_QH + kc * 32);
            ldsm4(al, qoff + OFF_QL - OFF_QH + OFF_QH + (OFF_QL - OFF_QH) - (OFF_QL - OFF_QH) + kc * 32 + (OFF_QL));
            // (the line above must address QL; rewritten plainly:)
            ldsm4(al, qoff + OFF_QL + kc * 32);
            #pragma unroll
            for (int jp = 0; jp < 4; jp++) {
                uint32_t baddr = kb + (jp*16 + brow) * (KSTR*2) + kc * 32 + bcsel;
                uint32_t bh[4], blr[4];
                ldsm4(bh, baddr);
                ldsm4(blr, baddr + KLOFF);
                mma16816(sf[2*jp],   ah, bh[0], bh[1]);
                mma16816(sf[2*jp+1], ah, bh[2], bh[3]);
                mma16816(sf[2*jp],   al, bh[0], bh[1]);
                mma16816(sf[2*jp+1], al, bh[2], bh[3]);
                mma16816(sf[2*jp],   ah, blr[0], blr[1]);
                mma16816(sf[2*jp+1], ah, blr[2], blr[3]);
            }
        }

        // ---- online softmax (rows: r0 = w*16 + l/4, r1 = r0+8) ----
        float mx0 = sf[0][0], mx1 = sf[0][2];
        #pragma unroll
        for (int j = 0; j < 8; j++) {
            mx0 = fmaxf(mx0, fmaxf(sf[j][0], sf[j][1]));
            mx1 = fmaxf(mx1, fmaxf(sf[j][2], sf[j][3]));
        }
        mx0 = fmaxf(mx0, __shfl_xor_sync(0xffffffffu, mx0, 1));
        mx0 = fmaxf(mx0, __shfl_xor_sync(0xffffffffu, mx0, 2));
        mx1 = fmaxf(mx1, __shfl_xor_sync(0xffffffffu, mx1, 1));
        mx1 = fmaxf(mx1, __shfl_xor_sync(0xffffffffu, mx1, 2));

        float mn0 = fmaxf(m0, mx0), mn1 = fmaxf(m1, mx1);
        float alpha0 = __expf(m0 - mn0), alpha1 = __expf(m1 - mn1);
        m0 = mn0; m1 = mn1;

        float s0 = 0.f, s1 = 0.f;
        #pragma unroll
        for (int j = 0; j < 8; j++) {
            sf[j][0] = __expf(sf[j][0] - mn0); s0 += sf[j][0];
            sf[j][1] = __expf(sf[j][1] - mn0); s0 += sf[j][1];
            sf[j][2] = __expf(sf[j][2] - mn1); s1 += sf[j][2];
            sf[j][3] = __expf(sf[j][3] - mn1); s1 += sf[j][3];
        }
        s0 += __shfl_xor_sync(0xffffffffu, s0, 1);
        s0 += __shfl_xor_sync(0xffffffffu, s0, 2);
        s1 += __shfl_xor_sync(0xffffffffu, s1, 1);
        s1 += __shfl_xor_sync(0xffffffffu, s1, 2);
        l0 = l0 * alpha0 + s0;
        l1 = l1 * alpha1 + s1;

        // rescale O
        #pragma unroll
        for (int n = 0; n < 16; n++) {
            of[n][0] *= alpha0; of[n][1] *= alpha0;
            of[n][2] *= alpha1; of[n][3] *= alpha1;
        }

        // ---- PV: O += P V  (P frags built from sf, B from transposed V) ----
        #pragma unroll
        for (int jk = 0; jk < 4; jk++) {
            uint32_t ph[4], pl4[4];
            {
                float p00 = sf[2*jk][0],   p01 = sf[2*jk][1];
                float p02 = sf[2*jk][2],   p03 = sf[2*jk][3];
                float p10 = sf[2*jk+1][0], p11 = sf[2*jk+1][1];
                float p12 = sf[2*jk+1][2], p13 = sf[2*jk+1][3];
                float h00 = __half2float(__float2half_rn(p00));
                float h01 = __half2float(__float2half_rn(p01));
                float h02 = __half2float(__float2half_rn(p02));
                float h03 = __half2float(__float2half_rn(p03));
                float h10 = __half2float(__float2half_rn(p10));
                float h11 = __half2float(__float2half_rn(p11));
                float h12 = __half2float(__float2half_rn(p12));
                float h13 = __half2float(__float2half_rn(p13));
                ph[0] = pack_h2(h00, h01); ph[1] = pack_h2(h02, h03);
                ph[2] = pack_h2(h10, h11); ph[3] = pack_h2(h12, h13);
                pl4[0] = pack_h2(p00-h00, p01-h01); pl4[1] = pack_h2(p02-h02, p03-h03);
                pl4[2] = pack_h2(p10-h10, p11-h11); pl4[3] = pack_h2(p12-h12, p13-h13);
            }
            #pragma unroll
            for (int np = 0; np < 8; np++) {
                uint32_t vaddr = vb + (np*16 + brow) * (VSTR*2) + jk * 32 + bcsel;
                uint32_t vh[4], vl[4];
                ldsm4(vh, vaddr);
                ldsm4(vl, vaddr + VLOFF);
                mma16816(of[2*np],   ph,  vh[0], vh[1]);
                mma16816(of[2*np+1], ph,  vh[2], vh[3]);
                mma16816(of[2*np],   pl4, vh[0], vh[1]);
                mma16816(of[2*np+1], pl4, vh[2], vh[3]);
                mma16816(of[2*np],   ph,  vl[0], vl[1]);
                mma16816(of[2*np+1], ph,  vl[2], vl[3]);
            }
        }

        CP_WAIT0();
        __syncthreads();
    }

    // ---- epilogue ----
    const int row0 = w*16 + (l >> 2);
    const float inv0 = 1.0f / l0, inv1 = 1.0f / l1;
    long long base0 = ((long long)b * SS + qi0 + row0) * DD;
    long long base1 = base0 + 8LL * DD;
    #pragma unroll
    for (int n = 0; n < 16; n++) {
        int cc = n*8 + (l & 3)*2;
        *(float2*)(out + base0 + cc) = make_float2(of[n][0]*inv0, of[n][1]*inv0);
        *(float2*)(out + base1 + cc) = make_float2(of[n][2]*inv1, of[n][3]*inv1);
    }
}

// ============================================================================
// launch
// ============================================================================
extern "C" void kernel_launch(void* const* d_in, const int* in_sizes, int n_in,
                              void* d_out, int out_size)
{
    const float* x  = (const float*)d_in[0];
    const float* Wq = (const float*)d_in[1];
    const float* bq = (const float*)d_in[2];
    const float* Wk = (const float*)d_in[3];
    const float* bk = (const float*)d_in[4];
    const float* Wv = (const float*)d_in[5];
    const float* bv = (const float*)d_in[6];
    float* out = (float*)d_out;

    qkv_gemm<<<dim3(MM / 128, 3), 256>>>(x, Wq, bq, Wk, bk, Wv, bv);

    cudaFuncSetAttribute(flash_attn, cudaFuncAttributeMaxDynamicSharedMemorySize,
                         FLASH_SMEM);
    flash_attn<<<dim3(SS / QT, BB), 256, FLASH_SMEM>>>(out);
}

// round 4
// speedup vs baseline: 3.6744x; 1.5111x over previous
#include <cuda_runtime.h>
#include <cuda_fp16.h>
#include <math.h>
#include <stdint.h>

#define BB 8
#define SS 4096
#define EE 2048
#define DD 128
#define MM (BB*SS)   // 32768

// fp16 hi/lo scratch (allocation-free __device__ globals)
__device__ __half g_qh[MM*DD];
__device__ __half g_ql[MM*DD];
__device__ __half g_kh[MM*DD];
__device__ __half g_kl[MM*DD];
__device__ __half g_vth[MM*DD];   // transposed: [b][d][s]
__device__ __half g_vtl[MM*DD];
// W transposed fp16 hi/lo: [y][d=128][e=2048]
__device__ __half g_wth[3*DD*EE];
__device__ __half g_wtl[3*DD*EE];

typedef unsigned long long u64;

__device__ __forceinline__ uint32_t pack_h2(float a, float b) {
    __half ha = __float2half_rn(a), hb = __float2half_rn(b);
    return ((uint32_t)__half_as_ushort(hb) << 16) | (uint32_t)__half_as_ushort(ha);
}
__device__ __forceinline__ uint32_t smem_u32(const void* p) {
    uint32_t a;
    asm("{ .reg .u64 t; cvta.to.shared.u64 t, %1; cvt.u32.u64 %0, t; }" : "=r"(a) : "l"(p));
    return a;
}

// ---- sm_80-era primitives (valid on base compute_103) ----
__device__ __forceinline__ void cp16(uint32_t dst, const void* src) {
    asm volatile("cp.async.cg.shared.global [%0], [%1], 16;" :: "r"(dst), "l"(src));
}
#define CP_COMMIT() asm volatile("cp.async.commit_group;" ::: "memory")
#define CP_WAIT0()  asm volatile("cp.async.wait_group 0;" ::: "memory")

__device__ __forceinline__ void ldsm4(uint32_t r[4], uint32_t addr) {
    asm volatile("ldmatrix.sync.aligned.m8n8.x4.shared.b16 {%0,%1,%2,%3}, [%4];"
        : "=r"(r[0]), "=r"(r[1]), "=r"(r[2]), "=r"(r[3]) : "r"(addr));
}
__device__ __forceinline__ void mma16816(float c[4], const uint32_t a[4],
                                          uint32_t b0, uint32_t b1) {
    asm volatile("mma.sync.aligned.m16n8k16.row.col.f32.f16.f16.f32 "
        "{%0,%1,%2,%3}, {%4,%5,%6,%7}, {%8,%9}, {%0,%1,%2,%3};"
        : "+f"(c[0]), "+f"(c[1]), "+f"(c[2]), "+f"(c[3])
        : "r"(a[0]), "r"(a[1]), "r"(a[2]), "r"(a[3]), "r"(b0), "r"(b1));
}

// ============================================================================
// Kernel 0: split W into transposed fp16 hi/lo.  out[y][d][e] from W[y][e][d].
// ============================================================================
__global__ __launch_bounds__(256) void split_w(
    const float* __restrict__ Wq, const float* __restrict__ Wk,
    const float* __restrict__ Wv)
{
    int idx = blockIdx.x * 256 + threadIdx.x;     // over 3*128*2048
    int y = idx >> 18;                             // /(128*2048)
    int rem = idx & ((DD*EE) - 1);
    int d = rem >> 11;                             // /2048
    int e = rem & (EE - 1);
    const float* W = (y == 0) ? Wq : (y == 1) ? Wk : Wv;
    float v = W[(long long)e * DD + d];
    __half h = __float2half_rn(v);
    g_wth[idx] = h;
    g_wtl[idx] = __float2half_rn(v - __half2float(h));
}

// ============================================================================
// Kernel 1: QKV projection via mma.sync, fp16 hi/lo 3-term split.
//   out = xh*Wh + xl*Wh + xh*Wl   (fp32 accum) + bias
// CTA: 64 M-rows x 128 N-cols, BK=64, 8 warps (4M x 2N), double-buffered.
// Epilogue emits fp16 hi/lo of q,k (row-major) and v (transposed [b][d][s]).
// ============================================================================
#define BK 64
#define XSTR 72                     // halfs per row (144B, conflict-free LDSM)
#define SXH 0
#define SXL (64*XSTR*2)             // 9216
#define SWH (2*64*XSTR*2)           // 18432
#define SWL (SWH + 128*XSTR*2)      // 36864
#define QBUF (SWL + 128*XSTR*2)     // 55296
#define QKV_SMEM (2*QBUF)           // 110592
#define NCHUNK (EE/BK)              // 32

__device__ __forceinline__ void qkv_stx(char* sm, int bufoff, const float4* xr, int tid) {
    int row = tid >> 2;
    int c0 = (tid & 3) * 4;          // half-col base within chunk
    #pragma unroll
    for (int i = 0; i < 4; i++) {
        float4 v = xr[i];
        float h0 = __half2float(__float2half_rn(v.x));
        float h1 = __half2float(__float2half_rn(v.y));
        float h2 = __half2float(__float2half_rn(v.z));
        float h3 = __half2float(__float2half_rn(v.w));
        uint2 uh = make_uint2(pack_h2(h0, h1), pack_h2(h2, h3));
        uint2 ul = make_uint2(pack_h2(v.x - h0, v.y - h1), pack_h2(v.z - h2, v.w - h3));
        int boff = row * (XSTR*2) + (c0 + 16*i) * 2;
        *(uint2*)(sm + bufoff + SXH + boff) = uh;
        *(uint2*)(sm + bufoff + SXL + boff) = ul;
    }
}

__device__ __forceinline__ void qkv_wcp(uint32_t smem, int bufoff, int y, int kt, int tid) {
    long long wbase = (long long)y * DD * EE + (long long)kt * BK;
    #pragma unroll
    for (int j = 0; j < 8; j++) {
        int idx = tid + j * 256;           // 0..2047
        int hl = idx >> 10;
        int rem = idx & 1023;
        int n = rem >> 3;                  // 0..127
        int c = rem & 7;                   // 16B chunk
        const __half* src = (hl ? g_wtl : g_wth) + wbase + (long long)n * EE + c * 8;
        uint32_t dst = smem + bufoff + (hl ? SWL : SWH) + n * (XSTR*2) + c * 16;
        cp16(dst, src);
    }
}

__global__ __launch_bounds__(256, 2) void qkv_mma(
    const float* __restrict__ x,
    const float* __restrict__ bq, const float* __restrict__ bk,
    const float* __restrict__ bv)
{
    extern __shared__ char sm[];
    const uint32_t smem = smem_u32(sm);
    const int tid = threadIdx.x;
    const int w = tid >> 5;
    const int l = tid & 31;
    const int y = blockIdx.y;
    const int m0 = blockIdx.x * 64;

    const int wm = (w >> 1) * 16;        // warp M base
    const int wn = (w & 1) * 64;         // warp N base
    const uint32_t brow  = (l & 7) + ((l >> 4) & 1) * 8;
    const uint32_t bcsel = ((l >> 3) & 1) * 16;

    // x loader: row = tid>>2, float4 cols (tid&3)*4 + 16*i
    const float* xg = x + (long long)(m0 + (tid >> 2)) * EE + (tid & 3) * 4;

    float of[8][4];
    #pragma unroll
    for (int n = 0; n < 8; n++)
        #pragma unroll
        for (int c = 0; c < 4; c++) of[n][c] = 0.f;

    // prologue: chunk 0
    float4 xr[4];
    #pragma unroll
    for (int i = 0; i < 4; i++) xr[i] = *(const float4*)(xg + 16*i);
    qkv_wcp(smem, 0, y, 0, tid);
    CP_COMMIT();
    qkv_stx(sm, 0, xr, tid);
    CP_WAIT0();
    __syncthreads();

    int buf = 0;
    for (int kt = 0; kt < NCHUNK; kt++) {
        const int nb = buf ^ 1;
        if (kt + 1 < NCHUNK) {
            #pragma unroll
            for (int i = 0; i < 4; i++)
                xr[i] = *(const float4*)(xg + (kt + 1) * BK + 16*i);
            qkv_wcp(smem, nb * QBUF, y, kt + 1, tid);
            CP_COMMIT();
        }

        const uint32_t aoff = smem + buf * QBUF + SXH
                            + (wm + (l & 15)) * (XSTR*2) + (l >> 4) * 16;
        const uint32_t wb = smem + buf * QBUF + SWH;
        #pragma unroll
        for (int kc = 0; kc < 4; kc++) {
            uint32_t ah[4], al[4];
            ldsm4(ah, aoff + kc * 32);
            ldsm4(al, aoff + (SXL - SXH) + kc * 32);
            #pragma unroll
            for (int jp = 0; jp < 4; jp++) {
                uint32_t baddr = wb + (wn + jp*16 + brow) * (XSTR*2) + kc * 32 + bcsel;
                uint32_t bh[4], bl2[4];
                ldsm4(bh, baddr);
                ldsm4(bl2, baddr + (SWL - SWH));
                mma16816(of[2*jp],   ah, bh[0], bh[1]);
                mma16816(of[2*jp+1], ah, bh[2], bh[3]);
                mma16816(of[2*jp],   al, bh[0], bh[1]);
                mma16816(of[2*jp+1], al, bh[2], bh[3]);
                mma16816(of[2*jp],   ah, bl2[0], bl2[1]);
                mma16816(of[2*jp+1], ah, bl2[2], bl2[3]);
            }
        }

        if (kt + 1 < NCHUNK) {
            qkv_stx(sm, nb * QBUF, xr, tid);
            CP_WAIT0();
        }
        __syncthreads();
        buf = nb;
    }

    // ---- epilogue: +bias, split hi/lo, store ----
    const float* bias = (y == 0) ? bq : (y == 1) ? bk : bv;
    const int row0 = m0 + wm + (l >> 2);
    const int row1 = row0 + 8;

    #pragma unroll
    for (int np = 0; np < 8; np++) {
        int col = wn + np * 8 + (l & 3) * 2;
        float b0 = bias[col], b1 = bias[col + 1];
        float v00 = of[np][0] + b0, v01 = of[np][1] + b1;   // row0
        float v10 = of[np][2] + b0, v11 = of[np][3] + b1;   // row1
        float h00 = __half2float(__float2half_rn(v00));
        float h01 = __half2float(__float2half_rn(v01));
        float h10 = __half2float(__float2half_rn(v10));
        float h11 = __half2float(__float2half_rn(v11));

        if (y < 2) {
            __half* ph = (y == 0) ? g_qh : g_kh;
            __half* pl = (y == 0) ? g_ql : g_kl;
            *(uint32_t*)&ph[(long long)row0 * DD + col] = pack_h2(h00, h01);
            *(uint32_t*)&ph[(long long)row1 * DD + col] = pack_h2(h10, h11);
            *(uint32_t*)&pl[(long long)row0 * DD + col] = pack_h2(v00 - h00, v01 - h01);
            *(uint32_t*)&pl[(long long)row1 * DD + col] = pack_h2(v10 - h10, v11 - h11);
        } else {
            // v transposed [b][d][s]
            int bbx0 = row0 >> 12, s0 = row0 & 4095;
            int bbx1 = row1 >> 12, s1 = row1 & 4095;
            long long i00 = ((long long)bbx0 * DD + col) * SS + s0;
            long long i01 = ((long long)bbx0 * DD + col + 1) * SS + s0;
            long long i10 = ((long long)bbx1 * DD + col) * SS + s1;
            long long i11 = ((long long)bbx1 * DD + col + 1) * SS + s1;
            g_vth[i00] = __float2half_rn(h00); g_vtl[i00] = __float2half_rn(v00 - h00);
            g_vth[i01] = __float2half_rn(h01); g_vtl[i01] = __float2half_rn(v01 - h01);
            g_vth[i10] = __float2half_rn(h10); g_vtl[i10] = __float2half_rn(v10 - h10);
            g_vth[i11] = __float2half_rn(h11); g_vtl[i11] = __float2half_rn(v11 - h11);
        }
    }
}

// ============================================================================
// Kernel 2: mma.sync flash attention (unchanged from round 3, cleaned).
// ============================================================================
#define QT 128
#define KT 64
#define NTILE (SS/KT)   // 64
#define QSTR 136
#define KSTR 136
#define VSTR 72

#define OFF_QH 0
#define OFF_QL (128*QSTR*2)             // 34816
#define OFF_K  (OFF_QL + 128*QSTR*2)    // 69632
#define KBUF   (64*KSTR*2*2)            // 34816
#define KLOFF  (64*KSTR*2)              // 17408
#define OFF_V  (OFF_K + 2*KBUF)         // 139264
#define VBUF   (128*VSTR*2*2)           // 36864
#define VLOFF  (128*VSTR*2)             // 18432
#define FLASH_SMEM (OFF_V + 2*VBUF)     // 212992

__device__ __forceinline__ void load_kv(uint32_t smem, int b, int kt, int buf, int tid) {
    long long tok0 = (long long)b * SS + (long long)kt * KT;
    #pragma unroll
    for (int it = 0; it < 8; it++) {
        int ci = tid + it * 256;
        int c = ci & 15;
        int row = (ci >> 4) & 63;
        const __half* src = ((ci < 1024) ? g_kh : g_kl) + (tok0 + row) * DD + c * 8;
        uint32_t dst = smem + OFF_K + buf * KBUF + ((ci < 1024) ? 0 : KLOFF)
                       + row * (KSTR*2) + c * 16;
        cp16(dst, src);
    }
    long long vbase = (long long)b * DD * SS + (long long)kt * KT;
    #pragma unroll
    for (int it = 0; it < 8; it++) {
        int ci = tid + it * 256;
        int c = ci & 7;
        int d = (ci >> 3) & 127;
        const __half* src = ((ci < 1024) ? g_vth : g_vtl) + vbase + (long long)d * SS + c * 8;
        uint32_t dst = smem + OFF_V + buf * VBUF + ((ci < 1024) ? 0 : VLOFF)
                       + d * (VSTR*2) + c * 16;
        cp16(dst, src);
    }
}

__global__ __launch_bounds__(256, 1) void flash_attn(float* __restrict__ out)
{
    extern __shared__ char sm[];
    const uint32_t smem = smem_u32(sm);
    const int tid = threadIdx.x;
    const int w = tid >> 5;
    const int l = tid & 31;
    const int b = blockIdx.y;
    const int qi0 = blockIdx.x * QT;

    {
        long long tok0 = (long long)b * SS + qi0;
        #pragma unroll
        for (int it = 0; it < 16; it++) {
            int ci = tid + it * 256;
            int c = ci & 15;
            int row = (ci >> 4) & 127;
            const __half* src = ((ci < 2048) ? g_qh : g_ql) + (tok0 + row) * DD + c * 8;
            uint32_t dst = smem + ((ci < 2048) ? OFF_QH : OFF_QL) + row * (QSTR*2) + c * 16;
            cp16(dst, src);
        }
    }
    load_kv(smem, b, 0, 0, tid);
    CP_COMMIT();
    CP_WAIT0();
    __syncthreads();

    float of[16][4];
    #pragma unroll
    for (int n = 0; n < 16; n++)
        #pragma unroll
        for (int c = 0; c < 4; c++) of[n][c] = 0.f;
    float m0 = -INFINITY, m1 = -INFINITY, l0 = 0.f, l1 = 0.f;

    const uint32_t qoff  = smem + (w*16 + (l & 15)) * (QSTR*2) + ((l >> 4) * 16);
    const uint32_t brow  = (l & 7) + ((l >> 4) & 1) * 8;
    const uint32_t bcsel = ((l >> 3) & 1) * 16;

    for (int t = 0; t < NTILE; t++) {
        if (t + 1 < NTILE) load_kv(smem, b, t + 1, (t + 1) & 1, tid);
        CP_COMMIT();

        const uint32_t kb = smem + OFF_K + (t & 1) * KBUF;
        const uint32_t vb = smem + OFF_V + (t & 1) * VBUF;

        float sf[8][4];
        #pragma unroll
        for (int j = 0; j < 8; j++)
            #pragma unroll
            for (int c = 0; c < 4; c++) sf[j][c] = 0.f;

        #pragma unroll
        for (int kc = 0; kc < 8; kc++) {
            uint32_t ah[4], al[4];
            ldsm4(ah, qoff + OFF_QH + kc * 32);
            ldsm4(al, qoff + OFF_QL + kc * 32);
            #pragma unroll
            for (int jp = 0; jp < 4; jp++) {
                uint32_t baddr = kb + (jp*16 + brow) * (KSTR*2) + kc * 32 + bcsel;
                uint32_t bh[4], blr[4];
                ldsm4(bh, baddr);
                ldsm4(blr, baddr + KLOFF);
                mma16816(sf[2*jp],   ah, bh[0], bh[1]);
                mma16816(sf[2*jp+1], ah, bh[2], bh[3]);
                mma16816(sf[2*jp],   al, bh[0], bh[1]);
                mma16816(sf[2*jp+1], al, bh[2], bh[3]);
                mma16816(sf[2*jp],   ah, blr[0], blr[1]);
                mma16816(sf[2*jp+1], ah, blr[2], blr[3]);
            }
        }

        float mx0 = sf[0][0], mx1 = sf[0][2];
        #pragma unroll
        for (int j = 0; j < 8; j++) {
            mx0 = fmaxf(mx0, fmaxf(sf[j][0], sf[j][1]));
            mx1 = fmaxf(mx1, fmaxf(sf[j][2], sf[j][3]));
        }
        mx0 = fmaxf(mx0, __shfl_xor_sync(0xffffffffu, mx0, 1));
        mx0 = fmaxf(mx0, __shfl_xor_sync(0xffffffffu, mx0, 2));
        mx1 = fmaxf(mx1, __shfl_xor_sync(0xffffffffu, mx1, 1));
        mx1 = fmaxf(mx1, __shfl_xor_sync(0xffffffffu, mx1, 2));

        float mn0 = fmaxf(m0, mx0), mn1 = fmaxf(m1, mx1);
        float alpha0 = __expf(m0 - mn0), alpha1 = __expf(m1 - mn1);
        m0 = mn0; m1 = mn1;

        float s0 = 0.f, s1 = 0.f;
        #pragma unroll
        for (int j = 0; j < 8; j++) {
            sf[j][0] = __expf(sf[j][0] - mn0); s0 += sf[j][0];
            sf[j][1] = __expf(sf[j][1] - mn0); s0 += sf[j][1];
            sf[j][2] = __expf(sf[j][2] - mn1); s1 += sf[j][2];
            sf[j][3] = __expf(sf[j][3] - mn1); s1 += sf[j][3];
        }
        s0 += __shfl_xor_sync(0xffffffffu, s0, 1);
        s0 += __shfl_xor_sync(0xffffffffu, s0, 2);
        s1 += __shfl_xor_sync(0xffffffffu, s1, 1);
        s1 += __shfl_xor_sync(0xffffffffu, s1, 2);
        l0 = l0 * alpha0 + s0;
        l1 = l1 * alpha1 + s1;

        #pragma unroll
        for (int n = 0; n < 16; n++) {
            of[n][0] *= alpha0; of[n][1] *= alpha0;
            of[n][2] *= alpha1; of[n][3] *= alpha1;
        }

        #pragma unroll
        for (int jk = 0; jk < 4; jk++) {
            uint32_t ph[4], pl4[4];
            {
                float p00 = sf[2*jk][0],   p01 = sf[2*jk][1];
                float p02 = sf[2*jk][2],   p03 = sf[2*jk][3];
                float p10 = sf[2*jk+1][0], p11 = sf[2*jk+1][1];
                float p12 = sf[2*jk+1][2], p13 = sf[2*jk+1][3];
                float h00 = __half2float(__float2half_rn(p00));
                float h01 = __half2float(__float2half_rn(p01));
                float h02 = __half2float(__float2half_rn(p02));
                float h03 = __half2float(__float2half_rn(p03));
                float h10 = __half2float(__float2half_rn(p10));
                float h11 = __half2float(__float2half_rn(p11));
                float h12 = __half2float(__float2half_rn(p12));
                float h13 = __half2float(__float2half_rn(p13));
                ph[0] = pack_h2(h00, h01); ph[1] = pack_h2(h02, h03);
                ph[2] = pack_h2(h10, h11); ph[3] = pack_h2(h12, h13);
                pl4[0] = pack_h2(p00-h00, p01-h01); pl4[1] = pack_h2(p02-h02, p03-h03);
                pl4[2] = pack_h2(p10-h10, p11-h11); pl4[3] = pack_h2(p12-h12, p13-h13);
            }
            #pragma unroll
            for (int np = 0; np < 8; np++) {
                uint32_t vaddr = vb + (np*16 + brow) * (VSTR*2) + jk * 32 + bcsel;
                uint32_t vh[4], vl[4];
                ldsm4(vh, vaddr);
                ldsm4(vl, vaddr + VLOFF);
                mma16816(of[2*np],   ph,  vh[0], vh[1]);
                mma16816(of[2*np+1], ph,  vh[2], vh[3]);
                mma16816(of[2*np],   pl4, vh[0], vh[1]);
                mma16816(of[2*np+1], pl4, vh[2], vh[3]);
                mma16816(of[2*np],   ph,  vl[0], vl[1]);
                mma16816(of[2*np+1], ph,  vl[2], vl[3]);
            }
        }

        CP_WAIT0();
        __syncthreads();
    }

    const int row0 = w*16 + (l >> 2);
    const float inv0 = 1.0f / l0, inv1 = 1.0f / l1;
    long long base0 = ((long long)b * SS + qi0 + row0) * DD;
    long long base1 = base0 + 8LL * DD;
    #pragma unroll
    for (int n = 0; n < 16; n++) {
        int cc = n*8 + (l & 3)*2;
        *(float2*)(out + base0 + cc) = make_float2(of[n][0]*inv0, of[n][1]*inv0);
        *(float2*)(out + base1 + cc) = make_float2(of[n][2]*inv1, of[n][3]*inv1);
    }
}

// ============================================================================
// launch
// ============================================================================
extern "C" void kernel_launch(void* const* d_in, const int* in_sizes, int n_in,
                              void* d_out, int out_size)
{
    const float* x  = (const float*)d_in[0];
    const float* Wq = (const float*)d_in[1];
    const float* bq = (const float*)d_in[2];
    const float* Wk = (const float*)d_in[3];
    const float* bk = (const float*)d_in[4];
    const float* Wv = (const float*)d_in[5];
    const float* bv = (const float*)d_in[6];
    float* out = (float*)d_out;

    split_w<<<(3*DD*EE)/256, 256>>>(Wq, Wk, Wv);

    cudaFuncSetAttribute(qkv_mma, cudaFuncAttributeMaxDynamicSharedMemorySize,
                         QKV_SMEM);
    qkv_mma<<<dim3(MM/64, 3), 256, QKV_SMEM>>>(x, bq, bk, bv);

    cudaFuncSetAttribute(flash_attn, cudaFuncAttributeMaxDynamicSharedMemorySize,
                         FLASH_SMEM);
    flash_attn<<<dim3(SS / QT, BB), 256, FLASH_SMEM>>>(out);
}

// round 5
// speedup vs baseline: 3.9510x; 1.0753x over previous
#include <cuda_runtime.h>
#include <cuda_fp16.h>
#include <math.h>
#include <stdint.h>

#define BB 8
#define SS 4096
#define EE 2048
#define DD 128
#define MM (BB*SS)   // 32768

// fp16 hi/lo scratch (allocation-free __device__ globals)
__device__ __half g_xh[MM*EE];    // x split hi (128MB)
__device__ __half g_xl[MM*EE];    // x split lo (128MB)
__device__ __half g_qh[MM*DD];
__device__ __half g_ql[MM*DD];
__device__ __half g_kh[MM*DD];
__device__ __half g_kl[MM*DD];
__device__ __half g_vth[MM*DD];   // v transposed [b][d][s], hi only
// W transposed fp16 hi/lo: [y][d=128][e=2048]
__device__ __half g_wth[3*DD*EE];
__device__ __half g_wtl[3*DD*EE];

typedef unsigned long long u64;

__device__ __forceinline__ uint32_t pack_h2(float a, float b) {
    __half ha = __float2half_rn(a), hb = __float2half_rn(b);
    return ((uint32_t)__half_as_ushort(hb) << 16) | (uint32_t)__half_as_ushort(ha);
}
__device__ __forceinline__ uint32_t smem_u32(const void* p) {
    uint32_t a;
    asm("{ .reg .u64 t; cvta.to.shared.u64 t, %1; cvt.u32.u64 %0, t; }" : "=r"(a) : "l"(p));
    return a;
}

// ---- sm_80-era primitives (valid on base compute_103) ----
__device__ __forceinline__ void cp16(uint32_t dst, const void* src) {
    asm volatile("cp.async.cg.shared.global [%0], [%1], 16;" :: "r"(dst), "l"(src));
}
#define CP_COMMIT() asm volatile("cp.async.commit_group;" ::: "memory")
#define CP_WAIT0()  asm volatile("cp.async.wait_group 0;" ::: "memory")

__device__ __forceinline__ void ldsm4(uint32_t r[4], uint32_t addr) {
    asm volatile("ldmatrix.sync.aligned.m8n8.x4.shared.b16 {%0,%1,%2,%3}, [%4];"
        : "=r"(r[0]), "=r"(r[1]), "=r"(r[2]), "=r"(r[3]) : "r"(addr));
}
__device__ __forceinline__ void mma16816(float c[4], const uint32_t a[4],
                                          uint32_t b0, uint32_t b1) {
    asm volatile("mma.sync.aligned.m16n8k16.row.col.f32.f16.f16.f32 "
        "{%0,%1,%2,%3}, {%4,%5,%6,%7}, {%8,%9}, {%0,%1,%2,%3};"
        : "+f"(c[0]), "+f"(c[1]), "+f"(c[2]), "+f"(c[3])
        : "r"(a[0]), "r"(a[1]), "r"(a[2]), "r"(a[3]), "r"(b0), "r"(b1));
}

// ============================================================================
// Kernel 0a: split x into fp16 hi/lo (row-major, same layout as x).
// ============================================================================
__global__ __launch_bounds__(256) void split_x(const float* __restrict__ x)
{
    long long idx = ((long long)blockIdx.x * 256 + threadIdx.x) * 4;
    float4 v = *(const float4*)(x + idx);
    float h0 = __half2float(__float2half_rn(v.x));
    float h1 = __half2float(__float2half_rn(v.y));
    float h2 = __half2float(__float2half_rn(v.z));
    float h3 = __half2float(__float2half_rn(v.w));
    *(uint2*)&g_xh[idx] = make_uint2(pack_h2(h0, h1), pack_h2(h2, h3));
    *(uint2*)&g_xl[idx] = make_uint2(pack_h2(v.x - h0, v.y - h1),
                                     pack_h2(v.z - h2, v.w - h3));
}

// ============================================================================
// Kernel 0b: split W into transposed fp16 hi/lo. out[y][d][e] from W[y][e][d].
// ============================================================================
__global__ __launch_bounds__(256) void split_w(
    const float* __restrict__ Wq, const float* __restrict__ Wk,
    const float* __restrict__ Wv)
{
    int idx = blockIdx.x * 256 + threadIdx.x;
    int y = idx >> 18;
    int rem = idx & ((DD*EE) - 1);
    int d = rem >> 11;
    int e = rem & (EE - 1);
    const float* W = (y == 0) ? Wq : (y == 1) ? Wk : Wv;
    float v = W[(long long)e * DD + d];
    __half h = __float2half_rn(v);
    g_wth[idx] = h;
    g_wtl[idx] = __float2half_rn(v - __half2float(h));
}

// ============================================================================
// Kernel 1: QKV projection via mma.sync, pure cp.async/ldsm/mma loop.
//   q,k: 3 terms (xh*Wh + xl*Wh + xh*Wl);  v: 2 terms (value path only needs
//   fp16-grade accuracy since PV consumes fp16(v)).
// CTA: 64 M x 128 N, BK=64, 8 warps (4M x 2N), double-buffered.
// ============================================================================
#define BK 64
#define XSTR 72
#define SXH 0
#define SXL (64*XSTR*2)             // 9216
#define SWH (2*64*XSTR*2)           // 18432
#define SWL (SWH + 128*XSTR*2)      // 36864
#define QBUF (SWL + 128*XSTR*2)     // 55296
#define QKV_SMEM (2*QBUF)           // 110592
#define NCHUNK (EE/BK)              // 32

__device__ __forceinline__ void qkv_ld(uint32_t smem, int bufoff, int y,
                                       int m0, int kt, int tid) {
    long long xbase = (long long)m0 * EE + (long long)kt * BK;
    #pragma unroll
    for (int j = 0; j < 4; j++) {
        int idx = tid + j * 256;            // 0..1023
        int hl = idx >> 9;
        int rem = idx & 511;
        int row = rem >> 3, c = rem & 7;
        const __half* src = (hl ? g_xl : g_xh) + xbase + (long long)row * EE + c * 8;
        cp16(smem + bufoff + (hl ? SXL : SXH) + row * (XSTR*2) + c * 16, src);
    }
    long long wbase = (long long)y * DD * EE + (long long)kt * BK;
    #pragma unroll
    for (int j = 0; j < 8; j++) {
        int idx = tid + j * 256;            // 0..2047
        int hl = idx >> 10;
        int rem = idx & 1023;
        int n = rem >> 3, c = rem & 7;
        const __half* src = (hl ? g_wtl : g_wth) + wbase + (long long)n * EE + c * 8;
        cp16(smem + bufoff + (hl ? SWL : SWH) + n * (XSTR*2) + c * 16, src);
    }
}

__global__ __launch_bounds__(256, 2) void qkv_mma(
    const float* __restrict__ bq, const float* __restrict__ bk,
    const float* __restrict__ bv)
{
    extern __shared__ char sm[];
    const uint32_t smem = smem_u32(sm);
    const int tid = threadIdx.x;
    const int w = tid >> 5;
    const int l = tid & 31;
    const int y = blockIdx.y;
    const int m0 = blockIdx.x * 64;

    const int wm = (w >> 1) * 16;
    const int wn = (w & 1) * 64;
    const uint32_t brow  = (l & 7) + ((l >> 4) & 1) * 8;
    const uint32_t bcsel = ((l >> 3) & 1) * 16;

    float of[8][4];
    #pragma unroll
    for (int n = 0; n < 8; n++)
        #pragma unroll
        for (int c = 0; c < 4; c++) of[n][c] = 0.f;

    qkv_ld(smem, 0, y, m0, 0, tid);
    CP_COMMIT();
    CP_WAIT0();
    __syncthreads();

    int buf = 0;
    for (int kt = 0; kt < NCHUNK; kt++) {
        const int nb = buf ^ 1;
        if (kt + 1 < NCHUNK) {
            qkv_ld(smem, nb * QBUF, y, m0, kt + 1, tid);
            CP_COMMIT();
        }

        const uint32_t aoff = smem + buf * QBUF + SXH
                            + (wm + (l & 15)) * (XSTR*2) + (l >> 4) * 16;
        const uint32_t wb = smem + buf * QBUF + SWH;
        #pragma unroll
        for (int kc = 0; kc < 4; kc++) {
            uint32_t ah[4], al[4];
            ldsm4(ah, aoff + kc * 32);
            ldsm4(al, aoff + (SXL - SXH) + kc * 32);
            #pragma unroll
            for (int jp = 0; jp < 4; jp++) {
                uint32_t baddr = wb + (wn + jp*16 + brow) * (XSTR*2) + kc * 32 + bcsel;
                uint32_t bh[4];
                ldsm4(bh, baddr);
                mma16816(of[2*jp],   ah, bh[0], bh[1]);
                mma16816(of[2*jp+1], ah, bh[2], bh[3]);
                mma16816(of[2*jp],   al, bh[0], bh[1]);
                mma16816(of[2*jp+1], al, bh[2], bh[3]);
                if (y != 2) {
                    uint32_t bl2[4];
                    ldsm4(bl2, baddr + (SWL - SWH));
                    mma16816(of[2*jp],   ah, bl2[0], bl2[1]);
                    mma16816(of[2*jp+1], ah, bl2[2], bl2[3]);
                }
            }
        }

        if (kt + 1 < NCHUNK) CP_WAIT0();
        __syncthreads();
        buf = nb;
    }

    // ---- epilogue: +bias, split hi/lo, store ----
    const float* bias = (y == 0) ? bq : (y == 1) ? bk : bv;
    const int row0 = m0 + wm + (l >> 2);
    const int row1 = row0 + 8;

    #pragma unroll
    for (int np = 0; np < 8; np++) {
        int col = wn + np * 8 + (l & 3) * 2;
        float b0 = bias[col], b1 = bias[col + 1];
        float v00 = of[np][0] + b0, v01 = of[np][1] + b1;
        float v10 = of[np][2] + b0, v11 = of[np][3] + b1;
        float h00 = __half2float(__float2half_rn(v00));
        float h01 = __half2float(__float2half_rn(v01));
        float h10 = __half2float(__float2half_rn(v10));
        float h11 = __half2float(__float2half_rn(v11));

        if (y < 2) {
            __half* ph = (y == 0) ? g_qh : g_kh;
            __half* pl = (y == 0) ? g_ql : g_kl;
            *(uint32_t*)&ph[(long long)row0 * DD + col] = pack_h2(h00, h01);
            *(uint32_t*)&ph[(long long)row1 * DD + col] = pack_h2(h10, h11);
            *(uint32_t*)&pl[(long long)row0 * DD + col] = pack_h2(v00 - h00, v01 - h01);
            *(uint32_t*)&pl[(long long)row1 * DD + col] = pack_h2(v10 - h10, v11 - h11);
        } else {
            int bbx0 = row0 >> 12, s0 = row0 & 4095;
            int bbx1 = row1 >> 12, s1 = row1 & 4095;
            g_vth[((long long)bbx0 * DD + col) * SS + s0]     = __float2half_rn(h00);
            g_vth[((long long)bbx0 * DD + col + 1) * SS + s0] = __float2half_rn(h01);
            g_vth[((long long)bbx1 * DD + col) * SS + s1]     = __float2half_rn(h10);
            g_vth[((long long)bbx1 * DD + col + 1) * SS + s1] = __float2half_rn(h11);
        }
    }
}

// ============================================================================
// Kernel 2: mma.sync flash attention.
//   S  = Qh*Kh + Ql*Kh + Qh*Kl   (3 terms, score path needs accuracy)
//   PV = Ph*Vh + Pl*Vh           (V rounded to fp16: error <= 2^-11 elementwise)
// ============================================================================
#define QT 128
#define KT 64
#define NTILE (SS/KT)   // 64
#define QSTR 136
#define KSTR 136
#define VSTR 72

#define OFF_QH 0
#define OFF_QL (128*QSTR*2)             // 34816
#define OFF_K  (OFF_QL + 128*QSTR*2)    // 69632
#define KBUF   (64*KSTR*2*2)            // 34816
#define KLOFF  (64*KSTR*2)              // 17408
#define OFF_V  (OFF_K + 2*KBUF)         // 139264
#define VBUF   (128*VSTR*2)             // 18432 (hi only)
#define FLASH_SMEM (OFF_V + 2*VBUF)     // 176128

__device__ __forceinline__ void load_kv(uint32_t smem, int b, int kt, int buf, int tid) {
    long long tok0 = (long long)b * SS + (long long)kt * KT;
    #pragma unroll
    for (int it = 0; it < 8; it++) {
        int ci = tid + it * 256;
        int c = ci & 15;
        int row = (ci >> 4) & 63;
        const __half* src = ((ci < 1024) ? g_kh : g_kl) + (tok0 + row) * DD + c * 8;
        uint32_t dst = smem + OFF_K + buf * KBUF + ((ci < 1024) ? 0 : KLOFF)
                       + row * (KSTR*2) + c * 16;
        cp16(dst, src);
    }
    long long vbase = (long long)b * DD * SS + (long long)kt * KT;
    #pragma unroll
    for (int it = 0; it < 4; it++) {
        int ci = tid + it * 256;           // 0..1023
        int c = ci & 7;
        int d = (ci >> 3) & 127;
        const __half* src = g_vth + vbase + (long long)d * SS + c * 8;
        uint32_t dst = smem + OFF_V + buf * VBUF + d * (VSTR*2) + c * 16;
        cp16(dst, src);
    }
}

__global__ __launch_bounds__(256, 1) void flash_attn(float* __restrict__ out)
{
    extern __shared__ char sm[];
    const uint32_t smem = smem_u32(sm);
    const int tid = threadIdx.x;
    const int w = tid >> 5;
    const int l = tid & 31;
    const int b = blockIdx.y;
    const int qi0 = blockIdx.x * QT;

    {
        long long tok0 = (long long)b * SS + qi0;
        #pragma unroll
        for (int it = 0; it < 16; it++) {
            int ci = tid + it * 256;
            int c = ci & 15;
            int row = (ci >> 4) & 127;
            const __half* src = ((ci < 2048) ? g_qh : g_ql) + (tok0 + row) * DD + c * 8;
            uint32_t dst = smem + ((ci < 2048) ? OFF_QH : OFF_QL) + row * (QSTR*2) + c * 16;
            cp16(dst, src);
        }
    }
    load_kv(smem, b, 0, 0, tid);
    CP_COMMIT();
    CP_WAIT0();
    __syncthreads();

    float of[16][4];
    #pragma unroll
    for (int n = 0; n < 16; n++)
        #pragma unroll
        for (int c = 0; c < 4; c++) of[n][c] = 0.f;
    float m0 = -INFINITY, m1 = -INFINITY, l0 = 0.f, l1 = 0.f;

    const uint32_t qoff  = smem + (w*16 + (l & 15)) * (QSTR*2) + ((l >> 4) * 16);
    const uint32_t brow  = (l & 7) + ((l >> 4) & 1) * 8;
    const uint32_t bcsel = ((l >> 3) & 1) * 16;

    for (int t = 0; t < NTILE; t++) {
        if (t + 1 < NTILE) load_kv(smem, b, t + 1, (t + 1) & 1, tid);
        CP_COMMIT();

        const uint32_t kb = smem + OFF_K + (t & 1) * KBUF;
        const uint32_t vb = smem + OFF_V + (t & 1) * VBUF;

        float sf[8][4];
        #pragma unroll
        for (int j = 0; j < 8; j++)
            #pragma unroll
            for (int c = 0; c < 4; c++) sf[j][c] = 0.f;

        #pragma unroll
        for (int kc = 0; kc < 8; kc++) {
            uint32_t ah[4], al[4];
            ldsm4(ah, qoff + OFF_QH + kc * 32);
            ldsm4(al, qoff + OFF_QL + kc * 32);
            #pragma unroll
            for (int jp = 0; jp < 4; jp++) {
                uint32_t baddr = kb + (jp*16 + brow) * (KSTR*2) + kc * 32 + bcsel;
                uint32_t bh[4], blr[4];
                ldsm4(bh, baddr);
                ldsm4(blr, baddr + KLOFF);
                mma16816(sf[2*jp],   ah, bh[0], bh[1]);
                mma16816(sf[2*jp+1], ah, bh[2], bh[3]);
                mma16816(sf[2*jp],   al, bh[0], bh[1]);
                mma16816(sf[2*jp+1], al, bh[2], bh[3]);
                mma16816(sf[2*jp],   ah, blr[0], blr[1]);
                mma16816(sf[2*jp+1], ah, blr[2], blr[3]);
            }
        }

        float mx0 = sf[0][0], mx1 = sf[0][2];
        #pragma unroll
        for (int j = 0; j < 8; j++) {
            mx0 = fmaxf(mx0, fmaxf(sf[j][0], sf[j][1]));
            mx1 = fmaxf(mx1, fmaxf(sf[j][2], sf[j][3]));
        }
        mx0 = fmaxf(mx0, __shfl_xor_sync(0xffffffffu, mx0, 1));
        mx0 = fmaxf(mx0, __shfl_xor_sync(0xffffffffu, mx0, 2));
        mx1 = fmaxf(mx1, __shfl_xor_sync(0xffffffffu, mx1, 1));
        mx1 = fmaxf(mx1, __shfl_xor_sync(0xffffffffu, mx1, 2));

        float mn0 = fmaxf(m0, mx0), mn1 = fmaxf(m1, mx1);
        float alpha0 = __expf(m0 - mn0), alpha1 = __expf(m1 - mn1);
        m0 = mn0; m1 = mn1;

        float s0 = 0.f, s1 = 0.f;
        #pragma unroll
        for (int j = 0; j < 8; j++) {
            sf[j][0] = __expf(sf[j][0] - mn0); s0 += sf[j][0];
            sf[j][1] = __expf(sf[j][1] - mn0); s0 += sf[j][1];
            sf[j][2] = __expf(sf[j][2] - mn1); s1 += sf[j][2];
            sf[j][3] = __expf(sf[j][3] - mn1); s1 += sf[j][3];
        }
        s0 += __shfl_xor_sync(0xffffffffu, s0, 1);
        s0 += __shfl_xor_sync(0xffffffffu, s0, 2);
        s1 += __shfl_xor_sync(0xffffffffu, s1, 1);
        s1 += __shfl_xor_sync(0xffffffffu, s1, 2);
        l0 = l0 * alpha0 + s0;
        l1 = l1 * alpha1 + s1;

        #pragma unroll
        for (int n = 0; n < 16; n++) {
            of[n][0] *= alpha0; of[n][1] *= alpha0;
            of[n][2] *= alpha1; of[n][3] *= alpha1;
        }

        #pragma unroll
        for (int jk = 0; jk < 4; jk++) {
            uint32_t ph[4], pl4[4];
            {
                float p00 = sf[2*jk][0],   p01 = sf[2*jk][1];
                float p02 = sf[2*jk][2],   p03 = sf[2*jk][3];
                float p10 = sf[2*jk+1][0], p11 = sf[2*jk+1][1];
                float p12 = sf[2*jk+1][2], p13 = sf[2*jk+1][3];
                float h00 = __half2float(__float2half_rn(p00));
                float h01 = __half2float(__float2half_rn(p01));
                float h02 = __half2float(__float2half_rn(p02));
                float h03 = __half2float(__float2half_rn(p03));
                float h10 = __half2float(__float2half_rn(p10));
                float h11 = __half2float(__float2half_rn(p11));
                float h12 = __half2float(__float2half_rn(p12));
                float h13 = __half2float(__float2half_rn(p13));
                ph[0] = pack_h2(h00, h01); ph[1] = pack_h2(h02, h03);
                ph[2] = pack_h2(h10, h11); ph[3] = pack_h2(h12, h13);
                pl4[0] = pack_h2(p00-h00, p01-h01); pl4[1] = pack_h2(p02-h02, p03-h03);
                pl4[2] = pack_h2(p10-h10, p11-h11); pl4[3] = pack_h2(p12-h12, p13-h13);
            }
            #pragma unroll
            for (int np = 0; np < 8; np++) {
                uint32_t vaddr = vb + (np*16 + brow) * (VSTR*2) + jk * 32 + bcsel;
                uint32_t vh[4];
                ldsm4(vh, vaddr);
                mma16816(of[2*np],   ph,  vh[0], vh[1]);
                mma16816(of[2*np+1], ph,  vh[2], vh[3]);
                mma16816(of[2*np],   pl4, vh[0], vh[1]);
                mma16816(of[2*np+1], pl4, vh[2], vh[3]);
            }
        }

        CP_WAIT0();
        __syncthreads();
    }

    const int row0 = w*16 + (l >> 2);
    const float inv0 = 1.0f / l0, inv1 = 1.0f / l1;
    long long base0 = ((long long)b * SS + qi0 + row0) * DD;
    long long base1 = base0 + 8LL * DD;
    #pragma unroll
    for (int n = 0; n < 16; n++) {
        int cc = n*8 + (l & 3)*2;
        *(float2*)(out + base0 + cc) = make_float2(of[n][0]*inv0, of[n][1]*inv0);
        *(float2*)(out + base1 + cc) = make_float2(of[n][2]*inv1, of[n][3]*inv1);
    }
}

// ============================================================================
// launch
// ============================================================================
extern "C" void kernel_launch(void* const* d_in, const int* in_sizes, int n_in,
                              void* d_out, int out_size)
{
    const float* x  = (const float*)d_in[0];
    const float* Wq = (const float*)d_in[1];
    const float* bq = (const float*)d_in[2];
    const float* Wk = (const float*)d_in[3];
    const float* bk = (const float*)d_in[4];
    const float* Wv = (const float*)d_in[5];
    const float* bv = (const float*)d_in[6];
    float* out = (float*)d_out;

    split_x<<<(long long)MM*EE/1024, 256>>>(x);
    split_w<<<(3*DD*EE)/256, 256>>>(Wq, Wk, Wv);

    cudaFuncSetAttribute(qkv_mma, cudaFuncAttributeMaxDynamicSharedMemorySize,
                         QKV_SMEM);
    qkv_mma<<<dim3(MM/64, 3), 256, QKV_SMEM>>>(bq, bk, bv);

    cudaFuncSetAttribute(flash_attn, cudaFuncAttributeMaxDynamicSharedMemorySize,
                         FLASH_SMEM);
    flash_attn<<<dim3(SS / QT, BB), 256, FLASH_SMEM>>>(out);
}